// round 2
// baseline (speedup 1.0000x reference)
#include <cuda_runtime.h>
#include <math.h>

#define B_ROWS 16384
#define NCLS   1000
#define CF     1280
#define SPLITK_COV 8
#define SPLITK_ORT 4

// ---------------- device scratch (static, allocation-free) ----------------
__device__ double g_acc[8];            // 0:nll 1:kl 2:l1 3:l2sq 4:cov 5:ortho
__device__ float  g_musum[CF];
__device__ float  g_covp[SPLITK_COV][CF * CF];       // lower-tri tiles only
__device__ float  g_ortp[SPLITK_ORT][1024 * 1024];

// ---------------- reduction helpers ----------------
__device__ __forceinline__ float warpSum(float v) {
    #pragma unroll
    for (int o = 16; o; o >>= 1) v += __shfl_xor_sync(0xffffffffu, v, o);
    return v;
}
__device__ __forceinline__ double warpSumD(double v) {
    #pragma unroll
    for (int o = 16; o; o >>= 1) v += __shfl_xor_sync(0xffffffffu, v, o);
    return v;
}
__device__ __forceinline__ float warpMax(float v) {
    #pragma unroll
    for (int o = 16; o; o >>= 1) v = fmaxf(v, __shfl_xor_sync(0xffffffffu, v, o));
    return v;
}

// ---------------- init ----------------
__global__ void k_init() {
    int t = blockIdx.x * blockDim.x + threadIdx.x;
    if (t < 8) g_acc[t] = 0.0;
    for (int j = t; j < CF; j += gridDim.x * blockDim.x) g_musum[j] = 0.f;
}

// ---------------- column sums of features ----------------
__global__ void k_colsum(const float* __restrict__ F) {
    int j  = blockIdx.x * 256 + threadIdx.x;          // 0..1279
    int r0 = blockIdx.y * (B_ROWS / 16);
    float s = 0.f;
    #pragma unroll 4
    for (int r = r0; r < r0 + B_ROWS / 16; ++r) s += F[(size_t)r * CF + j];
    atomicAdd(&g_musum[j], s);
}

// ---------------- per-row softmax stats (kl term) ----------------
__global__ __launch_bounds__(256) void k_kl(const float* __restrict__ F) {
    __shared__ float sx[CF];
    __shared__ float swk[8];
    __shared__ float sbc;
    int tid = threadIdx.x;
    int lane = tid & 31, wid = tid >> 5;
    const float* x = F + (size_t)blockIdx.x * CF;
    for (int j = tid; j < CF; j += 256) sx[j] = x[j];
    __syncthreads();

    // max
    float m = -3.4e38f;
    for (int j = tid; j < CF; j += 256) m = fmaxf(m, sx[j]);
    m = warpMax(m);
    if (lane == 0) swk[wid] = m;
    __syncthreads();
    if (tid == 0) {
        float v = swk[0];
        #pragma unroll
        for (int i = 1; i < 8; i++) v = fmaxf(v, swk[i]);
        sbc = v;
    }
    __syncthreads();
    m = sbc;
    __syncthreads();

    // sum exp
    float s = 0.f;
    for (int j = tid; j < CF; j += 256) s += __expf(sx[j] - m);
    s = warpSum(s);
    if (lane == 0) swk[wid] = s;
    __syncthreads();
    if (tid == 0) {
        float v = 0.f;
        #pragma unroll
        for (int i = 0; i < 8; i++) v += swk[i];
        sbc = m + __logf(v);
    }
    __syncthreads();
    float lse = sbc;
    __syncthreads();

    // sum L and sum P*L
    float sumL = 0.f, sumPL = 0.f;
    for (int j = tid; j < CF; j += 256) {
        float L = sx[j] - lse;
        sumL += L;
        sumPL = fmaf(__expf(L), L, sumPL);
    }
    sumL = warpSum(sumL);
    sumPL = warpSum(sumPL);
    if (lane == 0) { swk[wid] = sumL; }
    __syncthreads();
    if (tid == 0) {
        float a = 0.f;
        #pragma unroll
        for (int i = 0; i < 8; i++) a += swk[i];
        sbc = a;
    }
    __syncthreads();
    float totL = sbc;
    __syncthreads();
    if (lane == 0) { swk[wid] = sumPL; }
    __syncthreads();
    if (tid == 0) {
        float a = 0.f;
        #pragma unroll
        for (int i = 0; i < 8; i++) a += swk[i];
        double rowval = (double)CF * (double)a - (double)totL;
        atomicAdd(&g_acc[1], rowval);
    }
}

// ---------------- nll gather (dtype-robust: int64 or int32 target) -------
__global__ void k_nll(const float* __restrict__ out, const void* __restrict__ tgtraw) {
    __shared__ float swk[8];
    __shared__ int s_is64;
    const int* t32 = (const int*)tgtraw;
    int tid = threadIdx.x;

    if (tid == 0) {
        // int64 little-endian => odd 32-bit words are the (zero) high halves.
        // 64 ints probed stays inside the buffer for either dtype.
        int all0 = 1;
        #pragma unroll
        for (int k = 0; k < 32; k++) all0 &= (t32[2 * k + 1] == 0);
        s_is64 = all0;
    }
    __syncthreads();
    int is64 = s_is64;

    int gid = blockIdx.x * blockDim.x + tid;
    int stride = gridDim.x * blockDim.x;
    float v = 0.f;
    for (int b = gid; b < B_ROWS; b += stride) {
        int idx = is64 ? (int)((const long long*)tgtraw)[b] : t32[b];
        idx = min(max(idx, 0), NCLS - 1);       // never fault
        v += out[(size_t)b * NCLS + idx];
    }
    v = warpSum(v);
    if ((tid & 31) == 0) swk[tid >> 5] = v;
    __syncthreads();
    if (tid == 0) {
        float a = 0.f;
        int nw = blockDim.x >> 5;
        for (int i = 0; i < nw; i++) a += swk[i];
        atomicAdd(&g_acc[0], (double)a);
    }
}

// ---------------- weights L1 / L2^2 ----------------
__global__ void k_wsum(const float* __restrict__ W) {
    __shared__ float s1[8], s2[8];
    const int n = NCLS * CF;
    int tid = threadIdx.x;
    int gid = blockIdx.x * blockDim.x + tid;
    int stride = gridDim.x * blockDim.x;
    float a = 0.f, q = 0.f;
    for (int i = gid; i < n; i += stride) {
        float w = W[i];
        a += fabsf(w);
        q = fmaf(w, w, q);
    }
    a = warpSum(a); q = warpSum(q);
    if ((tid & 31) == 0) { s1[tid >> 5] = a; s2[tid >> 5] = q; }
    __syncthreads();
    if (tid == 0) {
        float aa = 0.f, qq = 0.f;
        #pragma unroll
        for (int i = 0; i < 8; i++) { aa += s1[i]; qq += s2[i]; }
        atomicAdd(&g_acc[2], (double)aa);
        atomicAdd(&g_acc[3], (double)qq);
    }
}

// ---------------- SYRK: partial G = F^T F, lower-triangle 128x128 tiles ----------------
__global__ __launch_bounds__(256) void k_cov(const float* __restrict__ F) {
    __shared__ alignas(16) float As[2][16][128];
    __shared__ alignas(16) float Bs[2][16][128];

    int t = blockIdx.x;
    int ti = 0;
    while ((ti + 1) * (ti + 2) / 2 <= t) ++ti;
    int tj = t - ti * (ti + 1) / 2;
    int i0 = ti * 128, j0 = tj * 128;
    int kbase = blockIdx.y * (B_ROWS / SPLITK_COV);
    const int KSTEPS = (B_ROWS / SPLITK_COV) / 16;   // 128

    int tid = threadIdx.x;
    int tx = tid & 15, ty = tid >> 4;
    int lk = tid >> 5;                 // k row 0..7
    int li = (tid * 4) & 127;          // col within tile

    const float* pa = F + (size_t)(kbase + lk) * CF + i0 + li;
    const float* pb = F + (size_t)(kbase + lk) * CF + j0 + li;

    float4 ra0, ra1, rb0, rb1;
    ra0 = *(const float4*)pa;            ra1 = *(const float4*)(pa + 8 * CF);
    rb0 = *(const float4*)pb;            rb1 = *(const float4*)(pb + 8 * CF);
    *(float4*)&As[0][lk][li] = ra0;      *(float4*)&As[0][lk + 8][li] = ra1;
    *(float4*)&Bs[0][lk][li] = rb0;      *(float4*)&Bs[0][lk + 8][li] = rb1;
    __syncthreads();

    float acc[8][8];
    #pragma unroll
    for (int m = 0; m < 8; m++)
        #pragma unroll
        for (int n = 0; n < 8; n++) acc[m][n] = 0.f;

    for (int s = 0; s < KSTEPS; ++s) {
        int cur = s & 1;
        if (s + 1 < KSTEPS) {
            const float* qa = pa + (size_t)(s + 1) * 16 * CF;
            const float* qb = pb + (size_t)(s + 1) * 16 * CF;
            ra0 = *(const float4*)qa;  ra1 = *(const float4*)(qa + 8 * CF);
            rb0 = *(const float4*)qb;  rb1 = *(const float4*)(qb + 8 * CF);
        }
        #pragma unroll
        for (int k = 0; k < 16; k++) {
            float ar[8], br[8];
            *(float4*)&ar[0] = *(const float4*)&As[cur][k][ty * 8];
            *(float4*)&ar[4] = *(const float4*)&As[cur][k][ty * 8 + 4];
            *(float4*)&br[0] = *(const float4*)&Bs[cur][k][tx * 8];
            *(float4*)&br[4] = *(const float4*)&Bs[cur][k][tx * 8 + 4];
            #pragma unroll
            for (int m = 0; m < 8; m++)
                #pragma unroll
                for (int n = 0; n < 8; n++)
                    acc[m][n] = fmaf(ar[m], br[n], acc[m][n]);
        }
        if (s + 1 < KSTEPS) {
            int nxt = cur ^ 1;
            *(float4*)&As[nxt][lk][li] = ra0;  *(float4*)&As[nxt][lk + 8][li] = ra1;
            *(float4*)&Bs[nxt][lk][li] = rb0;  *(float4*)&Bs[nxt][lk + 8][li] = rb1;
            __syncthreads();
        }
    }

    float* G = g_covp[blockIdx.y];
    #pragma unroll
    for (int m = 0; m < 8; m++) {
        int r = i0 + ty * 8 + m;
        float* row = G + (size_t)r * CF + j0 + tx * 8;
        *(float4*)row       = make_float4(acc[m][0], acc[m][1], acc[m][2], acc[m][3]);
        *(float4*)(row + 4) = make_float4(acc[m][4], acc[m][5], acc[m][6], acc[m][7]);
    }
}

// ---------------- GEMM: partial W W^T ----------------
__global__ __launch_bounds__(256) void k_ort(const float* __restrict__ W) {
    __shared__ alignas(16) float As[2][16][128];
    __shared__ alignas(16) float Bs[2][16][128];

    int ti = blockIdx.x >> 3, tj = blockIdx.x & 7;
    int i0 = ti * 128, j0 = tj * 128;
    int kbase = blockIdx.y * (CF / SPLITK_ORT);      // 320
    const int KSTEPS = (CF / SPLITK_ORT) / 16;       // 20

    int tid = threadIdx.x;
    int tx = tid & 15, ty = tid >> 4;
    int li  = tid >> 1;              // row within tile 0..127
    int lko = (tid & 1) * 8;         // k offset 0 or 8
    int ga = i0 + li, gb = j0 + li;
    bool va = ga < NCLS, vb = gb < NCLS;
    const float* pa = W + (size_t)(va ? ga : 0) * CF + kbase + lko;
    const float* pb = W + (size_t)(vb ? gb : 0) * CF + kbase + lko;

    float av[8], bv[8];
    {
        float4 x0 = va ? *(const float4*)pa       : make_float4(0, 0, 0, 0);
        float4 x1 = va ? *(const float4*)(pa + 4) : make_float4(0, 0, 0, 0);
        float4 y0 = vb ? *(const float4*)pb       : make_float4(0, 0, 0, 0);
        float4 y1 = vb ? *(const float4*)(pb + 4) : make_float4(0, 0, 0, 0);
        av[0]=x0.x; av[1]=x0.y; av[2]=x0.z; av[3]=x0.w; av[4]=x1.x; av[5]=x1.y; av[6]=x1.z; av[7]=x1.w;
        bv[0]=y0.x; bv[1]=y0.y; bv[2]=y0.z; bv[3]=y0.w; bv[4]=y1.x; bv[5]=y1.y; bv[6]=y1.z; bv[7]=y1.w;
    }
    #pragma unroll
    for (int q = 0; q < 8; q++) { As[0][lko + q][li] = av[q]; Bs[0][lko + q][li] = bv[q]; }
    __syncthreads();

    float acc[8][8];
    #pragma unroll
    for (int m = 0; m < 8; m++)
        #pragma unroll
        for (int n = 0; n < 8; n++) acc[m][n] = 0.f;

    for (int s = 0; s < KSTEPS; ++s) {
        int cur = s & 1;
        if (s + 1 < KSTEPS) {
            const float* qa = pa + (s + 1) * 16;
            const float* qb = pb + (s + 1) * 16;
            float4 x0 = va ? *(const float4*)qa       : make_float4(0, 0, 0, 0);
            float4 x1 = va ? *(const float4*)(qa + 4) : make_float4(0, 0, 0, 0);
            float4 y0 = vb ? *(const float4*)qb       : make_float4(0, 0, 0, 0);
            float4 y1 = vb ? *(const float4*)(qb + 4) : make_float4(0, 0, 0, 0);
            av[0]=x0.x; av[1]=x0.y; av[2]=x0.z; av[3]=x0.w; av[4]=x1.x; av[5]=x1.y; av[6]=x1.z; av[7]=x1.w;
            bv[0]=y0.x; bv[1]=y0.y; bv[2]=y0.z; bv[3]=y0.w; bv[4]=y1.x; bv[5]=y1.y; bv[6]=y1.z; bv[7]=y1.w;
        }
        #pragma unroll
        for (int k = 0; k < 16; k++) {
            float ar[8], br[8];
            *(float4*)&ar[0] = *(const float4*)&As[cur][k][ty * 8];
            *(float4*)&ar[4] = *(const float4*)&As[cur][k][ty * 8 + 4];
            *(float4*)&br[0] = *(const float4*)&Bs[cur][k][tx * 8];
            *(float4*)&br[4] = *(const float4*)&Bs[cur][k][tx * 8 + 4];
            #pragma unroll
            for (int m = 0; m < 8; m++)
                #pragma unroll
                for (int n = 0; n < 8; n++)
                    acc[m][n] = fmaf(ar[m], br[n], acc[m][n]);
        }
        if (s + 1 < KSTEPS) {
            int nxt = cur ^ 1;
            #pragma unroll
            for (int q = 0; q < 8; q++) { As[nxt][lko + q][li] = av[q]; Bs[nxt][lko + q][li] = bv[q]; }
            __syncthreads();
        }
    }

    float* G = g_ortp[blockIdx.y];
    #pragma unroll
    for (int m = 0; m < 8; m++) {
        int r = i0 + ty * 8 + m;
        float* row = G + (size_t)r * 1024 + j0 + tx * 8;
        *(float4*)row       = make_float4(acc[m][0], acc[m][1], acc[m][2], acc[m][3]);
        *(float4*)(row + 4) = make_float4(acc[m][4], acc[m][5], acc[m][6], acc[m][7]);
    }
}

// ---------------- cov loss reduce ----------------
__global__ void k_covred() {
    __shared__ double swk[8];
    const float invB = 1.0f / (float)B_ROWS;
    int tid = threadIdx.x;
    int gid = blockIdx.x * blockDim.x + tid;
    int stride = gridDim.x * blockDim.x;
    double local = 0.0;
    const int tot = CF * CF;
    for (int idx = gid; idx < tot; idx += stride) {
        int r = idx / CF, c = idx - r * CF;
        if (c > r) continue;
        float v = 0.f;
        #pragma unroll
        for (int s = 0; s < SPLITK_COV; s++) v += g_covp[s][idx];
        float mu_r = g_musum[r] * invB;
        float mu_c = g_musum[c] * invB;
        float cov = v * invB - mu_r * mu_c;
        float d = cov - (r == c ? 1.f : 0.f);
        local += (c < r ? 2.0 : 1.0) * (double)d * (double)d;
    }
    local = warpSumD(local);
    if ((tid & 31) == 0) swk[tid >> 5] = local;
    __syncthreads();
    if (tid == 0) {
        double a = 0.0;
        #pragma unroll
        for (int i = 0; i < 8; i++) a += swk[i];
        atomicAdd(&g_acc[4], a);
    }
}

// ---------------- ortho loss reduce ----------------
__global__ void k_ortred() {
    __shared__ double swk[8];
    int tid = threadIdx.x;
    int gid = blockIdx.x * blockDim.x + tid;
    int stride = gridDim.x * blockDim.x;
    double local = 0.0;
    const int tot = NCLS * NCLS;
    for (int idx = gid; idx < tot; idx += stride) {
        int r = idx / NCLS, c = idx - r * NCLS;
        float v = 0.f;
        #pragma unroll
        for (int s = 0; s < SPLITK_ORT; s++) v += g_ortp[s][(size_t)r * 1024 + c];
        float d = v - (r == c ? 1.f : 0.f);
        local += (double)d * (double)d;
    }
    local = warpSumD(local);
    if ((tid & 31) == 0) swk[tid >> 5] = local;
    __syncthreads();
    if (tid == 0) {
        double a = 0.0;
        #pragma unroll
        for (int i = 0; i < 8; i++) a += swk[i];
        atomicAdd(&g_acc[5], a);
    }
}

// ---------------- finalize ----------------
__global__ void k_final(float* out) {
    if (threadIdx.x == 0 && blockIdx.x == 0) {
        double nll = -g_acc[0] / (double)B_ROWS;
        double kl  =  g_acc[1] / (double)B_ROWS;
        double cov =  g_acc[4];
        double ort =  g_acc[5];
        double l1  =  g_acc[2];
        double l2  =  sqrt(g_acc[3]);
        out[0] = (float)(1.0 * nll + 0.2 * kl + 0.2 * cov + 0.1 * ort + 0.1 * l1 + 0.1 * l2);
    }
}

// ---------------- launch ----------------
extern "C" void kernel_launch(void* const* d_in, const int* in_sizes, int n_in,
                              void* d_out, int out_size) {
    const float* out_lp = nullptr;
    const void*  tgt = nullptr;
    const float* W = nullptr;
    const float* F = nullptr;
    for (int i = 0; i < n_in; i++) {
        long long sz = in_sizes[i];
        if (sz == (long long)B_ROWS * NCLS) out_lp = (const float*)d_in[i];
        else if (sz == B_ROWS)              tgt   = d_in[i];
        else if (sz == (long long)NCLS * CF) W    = (const float*)d_in[i];
        else if (sz == (long long)B_ROWS * CF) F  = (const float*)d_in[i];
    }
    if (!out_lp || !tgt || !W || !F) return;  // fail loudly via rel_err, not a fault

    k_init<<<5, 256>>>();
    k_colsum<<<dim3(CF / 256, 16), 256>>>(F);
    k_kl<<<B_ROWS, 256>>>(F);
    k_nll<<<64, 256>>>(out_lp, tgt);
    k_wsum<<<128, 256>>>(W);
    k_cov<<<dim3(55, SPLITK_COV), 256>>>(F);
    k_ort<<<dim3(64, SPLITK_ORT), 256>>>(W);
    k_covred<<<256, 256>>>();
    k_ortred<<<128, 256>>>();
    k_final<<<1, 32>>>((float*)d_out);
}

// round 4
// speedup vs baseline: 4.0600x; 4.0600x over previous
#include <cuda_runtime.h>
#include <cuda_bf16.h>
#include <math.h>
#include <stdint.h>

#define B_ROWS 16384
#define NCLS   1000
#define CF     1280
#define NPAD   1024

#define NT_COV 55                 // 10x10 lower-tri 128-tiles
#define NT_ORT 36                 // 8x8 lower-tri 128-tiles
#define SPLITC 2                  // split-K for cov
#define KSPLIT (B_ROWS / SPLITC)  // 8192
#define NSTEP_COV (KSPLIT / 64)   // 128
#define NSTEP_ORT (CF / 64)       // 20

#define STAGES      3
#define STAGE_BYTES 32768         // A(16KB)+B(16KB)
#define SMEM_MMA    (STAGES * STAGE_BYTES)

// ---------------- device scratch ----------------
__device__ double g_acc[8];            // 0:nll 2:l1 3:l2sq 4:cov 5:ortho
__device__ double g_klp[64];
__device__ float  g_musum[CF];
__device__ __align__(256) __nv_bfloat16 g_Ft[CF][B_ROWS];     // F^T bf16
__device__ __align__(256) __nv_bfloat16 g_Wb[NPAD][CF];       // W padded bf16
__device__ float g_covp[SPLITC][CF * CF];                     // split-K partials

// ---------------- helpers ----------------
__device__ __forceinline__ float warpSum(float v) {
    #pragma unroll
    for (int o = 16; o; o >>= 1) v += __shfl_xor_sync(0xffffffffu, v, o);
    return v;
}
__device__ __forceinline__ uint32_t smem_u32(const void* p) {
    uint32_t a;
    asm("{ .reg .u64 t; cvta.to.shared.u64 t, %1; cvt.u32.u64 %0, t; }" : "=r"(a) : "l"(p));
    return a;
}
__device__ __forceinline__ uint32_t sw128(uint32_t off) {
    return off ^ ((off >> 3) & 0x70);
}
__device__ __forceinline__ void cp16(uint32_t saddr, const void* g) {
    asm volatile("cp.async.cg.shared.global [%0], [%1], 16;" :: "r"(saddr), "l"(g) : "memory");
}
__device__ __forceinline__ void ldsm4(uint32_t* r, uint32_t addr) {
    asm volatile("ldmatrix.sync.aligned.m8n8.x4.shared.b16 {%0,%1,%2,%3}, [%4];"
                 : "=r"(r[0]), "=r"(r[1]), "=r"(r[2]), "=r"(r[3]) : "r"(addr));
}
__device__ __forceinline__ void mma16816(float* d, const uint32_t* a, uint32_t b0, uint32_t b1) {
    asm volatile(
        "mma.sync.aligned.m16n8k16.row.col.f32.bf16.bf16.f32 "
        "{%0,%1,%2,%3}, {%4,%5,%6,%7}, {%8,%9}, {%0,%1,%2,%3};"
        : "+f"(d[0]), "+f"(d[1]), "+f"(d[2]), "+f"(d[3])
        : "r"(a[0]), "r"(a[1]), "r"(a[2]), "r"(a[3]), "r"(b0), "r"(b1));
}

// ---------------- init ----------------
__global__ void k_init() {
    int t = blockIdx.x * blockDim.x + threadIdx.x;
    if (t < 8) g_acc[t] = 0.0;
    if (t < 64) g_klp[t] = 0.0;
    if (t < CF) g_musum[t] = 0.f;
}

// ---------------- W convert + L1/L2 ----------------
__global__ __launch_bounds__(256) void k_wconv(const float* __restrict__ W) {
    __shared__ float s1[8], s2[8];
    int tid = threadIdx.x;
    int gid = blockIdx.x * 256 + tid;
    int stride = gridDim.x * 256;
    float a = 0.f, q = 0.f;
    const int tot = NPAD * CF;
    for (int idx = gid; idx < tot; idx += stride) {
        int r = idx / CF, c = idx - r * CF;
        float w = 0.f;
        if (r < NCLS) {
            w = W[(size_t)r * CF + c];
            a += fabsf(w);
            q = fmaf(w, w, q);
        }
        g_Wb[r][c] = __float2bfloat16(w);
    }
    a = warpSum(a); q = warpSum(q);
    if ((tid & 31) == 0) { s1[tid >> 5] = a; s2[tid >> 5] = q; }
    __syncthreads();
    if (tid == 0) {
        float aa = 0.f, qq = 0.f;
        #pragma unroll
        for (int i = 0; i < 8; i++) { aa += s1[i]; qq += s2[i]; }
        atomicAdd(&g_acc[2], (double)aa);
        atomicAdd(&g_acc[3], (double)qq);
    }
}

// ---------------- F transpose -> bf16 + column sums ----------------
__global__ __launch_bounds__(256) void k_tconv(const float* __restrict__ F) {
    __shared__ float ts[32][33];
    int c0 = blockIdx.x * 32;
    int r0 = blockIdx.y * 32;
    int t = threadIdx.x;
    int tc = t & 31, tr = t >> 5;
    #pragma unroll
    for (int k = 0; k < 4; k++) {
        int r = tr + k * 8;
        ts[r][tc] = F[(size_t)(r0 + r) * CF + c0 + tc];
    }
    __syncthreads();
    if (t < 32) {
        float s = 0.f;
        #pragma unroll
        for (int r = 0; r < 32; r++) s += ts[r][t];
        atomicAdd(&g_musum[c0 + t], s);
    }
    int rp = (t & 15) * 2;
    int cc = t >> 4;
    #pragma unroll
    for (int k = 0; k < 2; k++) {
        int c = cc + k * 16;
        __nv_bfloat162 v = __floats2bfloat162_rn(ts[rp][c], ts[rp + 1][c]);
        *(__nv_bfloat162*)&g_Ft[c0 + c][r0 + rp] = v;
    }
}

// ---------------- KL single pass ----------------
__global__ __launch_bounds__(256) void k_kl(const float* __restrict__ F) {
    __shared__ float r1[8], r2[8], r3[8];
    int tid = threadIdx.x, lane = tid & 31, wid = tid >> 5;
    const float* x = F + (size_t)blockIdx.x * CF;
    float sx = 0.f, se = 0.f, sex = 0.f;
    for (int j = tid; j < CF; j += 256) {
        float v = x[j];
        float e = __expf(v);
        sx += v; se += e; sex = fmaf(e, v, sex);
    }
    sx = warpSum(sx); se = warpSum(se); sex = warpSum(sex);
    if (lane == 0) { r1[wid] = sx; r2[wid] = se; r3[wid] = sex; }
    __syncthreads();
    if (tid == 0) {
        float a = 0.f, b = 0.f, c = 0.f;
        #pragma unroll
        for (int i = 0; i < 8; i++) { a += r1[i]; b += r2[i]; c += r3[i]; }
        float rowval = (float)CF * (c / b) - a;
        atomicAdd(&g_klp[blockIdx.x & 63], (double)rowval);
    }
}

// ---------------- nll gather (dtype-robust) ----------------
__global__ void k_nll(const float* __restrict__ out, const void* __restrict__ tgtraw) {
    __shared__ float swk[8];
    __shared__ int s_is64;
    const int* t32 = (const int*)tgtraw;
    int tid = threadIdx.x;
    if (tid == 0) {
        int all0 = 1;
        #pragma unroll
        for (int k = 0; k < 32; k++) all0 &= (t32[2 * k + 1] == 0);
        s_is64 = all0;
    }
    __syncthreads();
    int is64 = s_is64;
    int gid = blockIdx.x * blockDim.x + tid;
    int stride = gridDim.x * blockDim.x;
    float v = 0.f;
    for (int b = gid; b < B_ROWS; b += stride) {
        int idx = is64 ? (int)((const long long*)tgtraw)[b] : t32[b];
        idx = min(max(idx, 0), NCLS - 1);
        v += out[(size_t)b * NCLS + idx];
    }
    v = warpSum(v);
    if ((tid & 31) == 0) swk[tid >> 5] = v;
    __syncthreads();
    if (tid == 0) {
        float a = 0.f;
        int nw = blockDim.x >> 5;
        for (int i = 0; i < nw; i++) a += swk[i];
        atomicAdd(&g_acc[0], (double)a);
    }
}

// ---------------- merged bf16 HMMA: cov SYRK (split-K 2) + ortho ---------
__device__ __forceinline__ void issue_loads(uint32_t sbase, int s, int step,
                                            const __nv_bfloat16* gA0,
                                            const __nv_bfloat16* gB0,
                                            int ld, int tid) {
    uint32_t tbase = sbase + (uint32_t)s * STAGE_BYTES;
    const __nv_bfloat16* gA = gA0 + step * 64;
    const __nv_bfloat16* gB = gB0 + step * 64;
    #pragma unroll
    for (int i = 0; i < 4; i++) {
        int q = tid + i * 256;            // 0..1023 -> A tile
        int r = q >> 3, u = q & 7;
        uint32_t so = sw128((uint32_t)(r * 128 + u * 16));
        cp16(tbase + so, gA + (size_t)r * ld + u * 8);
        cp16(tbase + 16384 + so, gB + (size_t)r * ld + u * 8);
    }
}

__global__ __launch_bounds__(256, 1) void k_mma2() {
    extern __shared__ char dsm[];
    uint32_t sbase = smem_u32(dsm);
    int tid = threadIdx.x, wid = tid >> 5, lane = tid & 31;
    int bid = blockIdx.x;

    bool is_cov = bid < SPLITC * NT_COV;
    int split = is_cov ? (bid >= NT_COV ? 1 : 0) : 0;
    int t = is_cov ? (bid - split * NT_COV) : (bid - SPLITC * NT_COV);
    int ti = 0;
    while ((ti + 1) * (ti + 2) / 2 <= t) ++ti;
    int tj = t - ti * (ti + 1) / 2;
    int i0 = ti * 128, j0 = tj * 128;

    const __nv_bfloat16* src = is_cov ? &g_Ft[0][0] : &g_Wb[0][0];
    const int ld = is_cov ? B_ROWS : CF;
    const int nstep = is_cov ? NSTEP_COV : NSTEP_ORT;
    const size_t koff = is_cov ? (size_t)split * KSPLIT : 0;

    const __nv_bfloat16* gA0 = src + (size_t)i0 * ld + koff;
    const __nv_bfloat16* gB0 = src + (size_t)j0 * ld + koff;

    int wm = wid >> 2, wn = wid & 3;   // warp tile: 64(m) x 32(n)

    float acc[16][4];
    #pragma unroll
    for (int i = 0; i < 16; i++)
        #pragma unroll
        for (int j = 0; j < 4; j++) acc[i][j] = 0.f;

    // A fragment smem address (per lane), varies by (mt, ks)
    uint32_t a_row = (uint32_t)(wm * 64 + (lane & 15));
    uint32_t a_hi  = (uint32_t)((lane >> 4) * 16);
    // B fragment address: pair p covers two n8 tiles
    uint32_t b_row = (uint32_t)(wn * 32 + (((lane >> 4) & 1) << 3) + (lane & 7));
    uint32_t b_hi  = (uint32_t)(((lane >> 3) & 1) * 16);

    // prologue
    int load_step = 0;
    #pragma unroll
    for (; load_step < STAGES; load_step++) {
        if (load_step < nstep) {
            issue_loads(sbase, load_step, load_step, gA0, gB0, ld, tid);
            asm volatile("cp.async.commit_group;" ::: "memory");
        }
    }

    for (int ms = 0; ms < nstep; ms++) {
        if (ms + STAGES <= nstep) asm volatile("cp.async.wait_group %0;" :: "n"(STAGES - 1) : "memory");
        else                      asm volatile("cp.async.wait_group 0;" ::: "memory");
        __syncthreads();

        int s = ms % STAGES;
        uint32_t abase = sbase + (uint32_t)s * STAGE_BYTES;
        uint32_t bbase = abase + 16384;

        #pragma unroll
        for (int ks = 0; ks < 4; ks++) {
            uint32_t afr[4][4];
            #pragma unroll
            for (int mt = 0; mt < 4; mt++) {
                uint32_t off = (a_row + mt * 16) * 128 + ks * 32 + a_hi;
                ldsm4(afr[mt], abase + sw128(off));
            }
            uint32_t bfr[2][4];
            #pragma unroll
            for (int p = 0; p < 2; p++) {
                uint32_t off = (b_row + p * 16) * 128 + ks * 32 + b_hi;
                ldsm4(bfr[p], bbase + sw128(off));
            }
            #pragma unroll
            for (int mt = 0; mt < 4; mt++)
                #pragma unroll
                for (int nt = 0; nt < 4; nt++)
                    mma16816(acc[mt * 4 + nt], afr[mt],
                             bfr[nt >> 1][(nt & 1) * 2], bfr[nt >> 1][(nt & 1) * 2 + 1]);
        }
        __syncthreads();   // all warps done reading stage s before refill

        if (load_step < nstep) {
            issue_loads(sbase, load_step % STAGES, load_step, gA0, gB0, ld, tid);
            asm volatile("cp.async.commit_group;" ::: "memory");
            load_step++;
        }
    }

    // ---------------- epilogue ----------------
    if (is_cov) {
        float* G = g_covp[split];
        #pragma unroll
        for (int mt = 0; mt < 4; mt++) {
            int gr0 = i0 + wm * 64 + mt * 16 + (lane >> 2);
            #pragma unroll
            for (int nt = 0; nt < 4; nt++) {
                int gc = j0 + wn * 32 + nt * 8 + (lane & 3) * 2;
                float* p0 = G + (size_t)gr0 * CF + gc;
                float* p1 = G + (size_t)(gr0 + 8) * CF + gc;
                *(float2*)p0 = make_float2(acc[mt * 4 + nt][0], acc[mt * 4 + nt][1]);
                *(float2*)p1 = make_float2(acc[mt * 4 + nt][2], acc[mt * 4 + nt][3]);
            }
        }
    } else {
        float lsum = 0.f;
        #pragma unroll
        for (int mt = 0; mt < 4; mt++) {
            int gr0 = i0 + wm * 64 + mt * 16 + (lane >> 2);
            #pragma unroll
            for (int nt = 0; nt < 4; nt++) {
                int gc = j0 + wn * 32 + nt * 8 + (lane & 3) * 2;
                #pragma unroll
                for (int e = 0; e < 4; e++) {
                    int gr = gr0 + (e >> 1) * 8;
                    int gcc = gc + (e & 1);
                    if (gr < NCLS && gcc < NCLS) {
                        float d = acc[mt * 4 + nt][e] - (gr == gcc ? 1.f : 0.f);
                        lsum = fmaf(d, d, lsum);
                    }
                }
            }
        }
        lsum = warpSum(lsum);
        __shared__ float red[8];
        if ((lane) == 0) red[wid] = lsum;
        __syncthreads();
        if (tid == 0) {
            float a = 0.f;
            #pragma unroll
            for (int i = 0; i < 8; i++) a += red[i];
            float w = (ti == tj) ? 1.f : 2.f;
            atomicAdd(&g_acc[5], (double)(a * w));
        }
    }
}

// ---------------- cov loss reduce ----------------
__global__ void k_covred() {
    __shared__ double swk[8];
    const float invB = 1.0f / (float)B_ROWS;
    int tid = threadIdx.x;
    int gid = blockIdx.x * blockDim.x + tid;
    int stride = gridDim.x * blockDim.x;
    double local = 0.0;
    const int tot = CF * CF;
    for (int idx = gid; idx < tot; idx += stride) {
        int r = idx / CF, c = idx - r * CF;
        if (c > r) continue;
        float v = g_covp[0][idx] + g_covp[1][idx];
        float mu_r = g_musum[r] * invB;
        float mu_c = g_musum[c] * invB;
        float cov = fmaf(v, invB, -mu_r * mu_c);
        float d = cov - (r == c ? 1.f : 0.f);
        local += (c < r ? 2.0 : 1.0) * (double)d * (double)d;
    }
    #pragma unroll
    for (int o = 16; o; o >>= 1) local += __shfl_xor_sync(0xffffffffu, local, o);
    if ((tid & 31) == 0) swk[tid >> 5] = local;
    __syncthreads();
    if (tid == 0) {
        double a = 0.0;
        #pragma unroll
        for (int i = 0; i < 8; i++) a += swk[i];
        atomicAdd(&g_acc[4], a);
    }
}

// ---------------- finalize ----------------
__global__ void k_final(float* out) {
    if (threadIdx.x == 0 && blockIdx.x == 0) {
        double kl = 0.0;
        for (int i = 0; i < 64; i++) kl += g_klp[i];
        double nll = -g_acc[0] / (double)B_ROWS;
        kl = kl / (double)B_ROWS;
        double cov = g_acc[4];
        double ort = g_acc[5];
        double l1  = g_acc[2];
        double l2  = sqrt(g_acc[3]);
        out[0] = (float)(1.0 * nll + 0.2 * kl + 0.2 * cov + 0.1 * ort + 0.1 * l1 + 0.1 * l2);
    }
}

// ---------------- launch ----------------
extern "C" void kernel_launch(void* const* d_in, const int* in_sizes, int n_in,
                              void* d_out, int out_size) {
    const float* out_lp = nullptr;
    const void*  tgt = nullptr;
    const float* W = nullptr;
    const float* F = nullptr;
    for (int i = 0; i < n_in; i++) {
        long long sz = in_sizes[i];
        if (sz == (long long)B_ROWS * NCLS) out_lp = (const float*)d_in[i];
        else if (sz == B_ROWS)              tgt   = d_in[i];
        else if (sz == (long long)NCLS * CF) W    = (const float*)d_in[i];
        else if (sz == (long long)B_ROWS * CF) F  = (const float*)d_in[i];
    }
    if (!out_lp || !tgt || !W || !F) return;

    static int smem_set = 0;
    if (!smem_set) {
        cudaFuncSetAttribute(k_mma2, cudaFuncAttributeMaxDynamicSharedMemorySize, SMEM_MMA);
        smem_set = 1;
    }

    k_init<<<5, 256>>>();
    k_wconv<<<160, 256>>>(W);
    k_tconv<<<dim3(CF / 32, B_ROWS / 32), 256>>>(F);
    k_kl<<<B_ROWS, 256>>>(F);
    k_nll<<<64, 256>>>(out_lp, tgt);
    k_mma2<<<SPLITC * NT_COV + NT_ORT, 256, SMEM_MMA>>>();
    k_covred<<<256, 256>>>();
    k_final<<<1, 32>>>((float*)d_out);
}

// round 5
// speedup vs baseline: 4.4447x; 1.0947x over previous
#include <cuda_runtime.h>
#include <cuda_bf16.h>
#include <cuda_fp8.h>
#include <math.h>
#include <stdint.h>

#define B_ROWS 16384
#define NCLS   1000
#define CF     1280
#define NPAD   1024

#define NT_COV 55                 // 10x10 lower-tri 128-tiles
#define NT_ORT 36                 // 8x8 lower-tri 128-tiles
#define SPLITC 2
#define KSPLIT (B_ROWS / SPLITC)  // 8192
#define NSTEP_COV (KSPLIT / 128)  // 64   (K-step = 128 fp8 elements = 128B row)
#define NSTEP_ORT (CF / 128)      // 10

#define STAGES      3
#define STAGE_BYTES 32768         // A(16KB fp8 128x128) + B(16KB)
#define SMEM_MMA    (STAGES * STAGE_BYTES)

#define WSCALE 64.0f              // W quant scale (exact power of 2)
#define WSCALE2_INV (1.0f / 4096.0f)

// ---------------- device scratch ----------------
__device__ double g_acc[8];            // 0:nll 2:l1 3:l2sq 4:cov 5:ortho
__device__ double g_klp[64];
__device__ float  g_musum[CF];
__device__ __align__(256) uint8_t g_Ft8[CF][B_ROWS];     // F^T e4m3
__device__ __align__(256) uint8_t g_Wb8[NPAD][CF];       // W*64 e4m3, zero-padded
__device__ float g_covp[SPLITC][CF * CF];

// ---------------- helpers ----------------
__device__ __forceinline__ float warpSum(float v) {
    #pragma unroll
    for (int o = 16; o; o >>= 1) v += __shfl_xor_sync(0xffffffffu, v, o);
    return v;
}
__device__ __forceinline__ uint32_t smem_u32(const void* p) {
    uint32_t a;
    asm("{ .reg .u64 t; cvta.to.shared.u64 t, %1; cvt.u32.u64 %0, t; }" : "=r"(a) : "l"(p));
    return a;
}
__device__ __forceinline__ uint32_t sw128(uint32_t off) {
    return off ^ ((off >> 3) & 0x70);
}
__device__ __forceinline__ void cp16(uint32_t saddr, const void* g) {
    asm volatile("cp.async.cg.shared.global [%0], [%1], 16;" :: "r"(saddr), "l"(g) : "memory");
}
__device__ __forceinline__ void ldsm4(uint32_t* r, uint32_t addr) {
    asm volatile("ldmatrix.sync.aligned.m8n8.x4.shared.b16 {%0,%1,%2,%3}, [%4];"
                 : "=r"(r[0]), "=r"(r[1]), "=r"(r[2]), "=r"(r[3]) : "r"(addr));
}
__device__ __forceinline__ void mma_fp8(float* d, const uint32_t* a, uint32_t b0, uint32_t b1) {
    asm volatile(
        "mma.sync.aligned.m16n8k32.row.col.f32.e4m3.e4m3.f32 "
        "{%0,%1,%2,%3}, {%4,%5,%6,%7}, {%8,%9}, {%0,%1,%2,%3};"
        : "+f"(d[0]), "+f"(d[1]), "+f"(d[2]), "+f"(d[3])
        : "r"(a[0]), "r"(a[1]), "r"(a[2]), "r"(a[3]), "r"(b0), "r"(b1));
}
__device__ __forceinline__ uint8_t to_e4m3(float v) {
    return (uint8_t)__nv_cvt_float_to_fp8(v, __NV_SATFINITE, __NV_E4M3);
}

// ---------------- init ----------------
__global__ void k_init() {
    int t = blockIdx.x * blockDim.x + threadIdx.x;
    if (t < 8) g_acc[t] = 0.0;
    if (t < 64) g_klp[t] = 0.0;
    if (t < CF) g_musum[t] = 0.f;
}

// ---------------- W convert (x64 -> e4m3) + L1/L2 ----------------
__global__ __launch_bounds__(256) void k_wconv(const float* __restrict__ W) {
    __shared__ float s1[8], s2[8];
    int tid = threadIdx.x;
    int gid = blockIdx.x * 256 + tid;
    int stride = gridDim.x * 256;
    float a = 0.f, q = 0.f;
    const int tot = NPAD * CF;
    for (int idx = gid; idx < tot; idx += stride) {
        int r = idx / CF, c = idx - r * CF;
        float w = 0.f;
        if (r < NCLS) {
            w = W[(size_t)r * CF + c];
            a += fabsf(w);
            q = fmaf(w, w, q);
        }
        g_Wb8[r][c] = to_e4m3(w * WSCALE);
    }
    a = warpSum(a); q = warpSum(q);
    if ((tid & 31) == 0) { s1[tid >> 5] = a; s2[tid >> 5] = q; }
    __syncthreads();
    if (tid == 0) {
        float aa = 0.f, qq = 0.f;
        #pragma unroll
        for (int i = 0; i < 8; i++) { aa += s1[i]; qq += s2[i]; }
        atomicAdd(&g_acc[2], (double)aa);
        atomicAdd(&g_acc[3], (double)qq);
    }
}

// ---------------- fused F pass: KL stats + colsum + transpose->e4m3 -----
// block = 32 rows x 1280 cols (40 chunks of 32x32); 256 threads.
__global__ __launch_bounds__(256) void k_fpass(const float* __restrict__ F) {
    __shared__ float ts[32][33];
    int r0 = blockIdx.x * 32;
    int t = threadIdx.x;
    int lane = t & 31, wid = t >> 5;

    // per-thread KL partials for rows r0+wid+8k (k=0..3), cols = lane stripe
    float sx[4] = {0, 0, 0, 0}, se[4] = {0, 0, 0, 0}, sex[4] = {0, 0, 0, 0};

    for (int ch = 0; ch < 40; ch++) {
        int c0 = ch * 32;
        float v[4];
        #pragma unroll
        for (int k = 0; k < 4; k++) {
            int r = wid + k * 8;
            v[k] = F[(size_t)(r0 + r) * CF + c0 + lane];
            float e = __expf(v[k]);
            sx[k] += v[k]; se[k] += e; sex[k] = fmaf(e, v[k], sex[k]);
            ts[r][lane] = v[k];
        }
        __syncthreads();
        // transposed fp8 write: thread -> col c = t>>3, rows (t&7)*4..+3
        {
            int c = t >> 3, rseg = (t & 7) * 4;
            uchar4 o;
            o.x = to_e4m3(ts[rseg + 0][c]);
            o.y = to_e4m3(ts[rseg + 1][c]);
            o.z = to_e4m3(ts[rseg + 2][c]);
            o.w = to_e4m3(ts[rseg + 3][c]);
            *(uchar4*)&g_Ft8[c0 + c][r0 + rseg] = o;
        }
        // colsum: warp 0 reduces columns of the tile
        if (wid == 0) {
            float s = 0.f;
            #pragma unroll
            for (int r = 0; r < 32; r++) s += ts[r][lane];
            atomicAdd(&g_musum[c0 + lane], s);
        }
        __syncthreads();
    }

    // KL row reduce: warp handles rows r0+wid+8k
    float tot = 0.f;
    #pragma unroll
    for (int k = 0; k < 4; k++) {
        float a = warpSum(sx[k]);
        float b = warpSum(se[k]);
        float c = warpSum(sex[k]);
        tot += (float)CF * (c / b) - a;
    }
    if (lane == 0) atomicAdd(&g_klp[(blockIdx.x * 8 + wid) & 63], (double)tot);
}

// ---------------- nll gather (dtype-robust) ----------------
__global__ void k_nll(const float* __restrict__ out, const void* __restrict__ tgtraw) {
    __shared__ float swk[8];
    __shared__ int s_is64;
    const int* t32 = (const int*)tgtraw;
    int tid = threadIdx.x;
    if (tid == 0) {
        int all0 = 1;
        #pragma unroll
        for (int k = 0; k < 32; k++) all0 &= (t32[2 * k + 1] == 0);
        s_is64 = all0;
    }
    __syncthreads();
    int is64 = s_is64;
    int gid = blockIdx.x * blockDim.x + tid;
    int stride = gridDim.x * blockDim.x;
    float v = 0.f;
    for (int b = gid; b < B_ROWS; b += stride) {
        int idx = is64 ? (int)((const long long*)tgtraw)[b] : t32[b];
        idx = min(max(idx, 0), NCLS - 1);
        v += out[(size_t)b * NCLS + idx];
    }
    v = warpSum(v);
    if ((tid & 31) == 0) swk[tid >> 5] = v;
    __syncthreads();
    if (tid == 0) {
        float a = 0.f;
        int nw = blockDim.x >> 5;
        for (int i = 0; i < nw; i++) a += swk[i];
        atomicAdd(&g_acc[0], (double)a);
    }
}

// ---------------- merged fp8 MMA: cov SYRK (split-K 2) + ortho ----------
__device__ __forceinline__ void issue_loads(uint32_t sbase, int s, int step,
                                            const uint8_t* gA0, const uint8_t* gB0,
                                            int ld, int tid) {
    uint32_t tbase = sbase + (uint32_t)s * STAGE_BYTES;
    const uint8_t* gA = gA0 + (size_t)step * 128;
    const uint8_t* gB = gB0 + (size_t)step * 128;
    #pragma unroll
    for (int i = 0; i < 4; i++) {
        int q = tid + i * 256;            // 0..1023
        int r = q >> 3, u = q & 7;        // 128 rows x 8 chunks(16B)
        uint32_t so = sw128((uint32_t)(r * 128 + u * 16));
        cp16(tbase + so, gA + (size_t)r * ld + u * 16);
        cp16(tbase + 16384 + so, gB + (size_t)r * ld + u * 16);
    }
}

__global__ __launch_bounds__(256, 1) void k_mma3() {
    extern __shared__ char dsm[];
    uint32_t sbase = smem_u32(dsm);
    int tid = threadIdx.x, wid = tid >> 5, lane = tid & 31;
    int bid = blockIdx.x;

    bool is_cov = bid < SPLITC * NT_COV;
    int split = is_cov ? (bid >= NT_COV ? 1 : 0) : 0;
    int t = is_cov ? (bid - split * NT_COV) : (bid - SPLITC * NT_COV);
    int ti = 0;
    while ((ti + 1) * (ti + 2) / 2 <= t) ++ti;
    int tj = t - ti * (ti + 1) / 2;
    int i0 = ti * 128, j0 = tj * 128;

    const uint8_t* src = is_cov ? &g_Ft8[0][0] : &g_Wb8[0][0];
    const int ld = is_cov ? B_ROWS : CF;
    const int nstep = is_cov ? NSTEP_COV : NSTEP_ORT;
    const size_t koff = is_cov ? (size_t)split * KSPLIT : 0;

    const uint8_t* gA0 = src + (size_t)i0 * ld + koff;
    const uint8_t* gB0 = src + (size_t)j0 * ld + koff;

    int wm = wid >> 2, wn = wid & 3;   // warp tile 64(m) x 32(n)

    float acc[16][4];
    #pragma unroll
    for (int i = 0; i < 16; i++)
        #pragma unroll
        for (int j = 0; j < 4; j++) acc[i][j] = 0.f;

    // fragment smem addressing (rows of 128B; identical pattern to bf16 k16)
    uint32_t a_row = (uint32_t)(wm * 64 + (lane & 15));
    uint32_t a_hi  = (uint32_t)((lane >> 4) * 16);
    uint32_t b_row = (uint32_t)(wn * 32 + (((lane >> 4) & 1) << 3) + (lane & 7));
    uint32_t b_hi  = (uint32_t)(((lane >> 3) & 1) * 16);

    int load_step = 0;
    #pragma unroll
    for (; load_step < STAGES; load_step++) {
        if (load_step < nstep) {
            issue_loads(sbase, load_step, load_step, gA0, gB0, ld, tid);
            asm volatile("cp.async.commit_group;" ::: "memory");
        }
    }

    for (int ms = 0; ms < nstep; ms++) {
        if (ms + STAGES <= nstep) asm volatile("cp.async.wait_group %0;" :: "n"(STAGES - 1) : "memory");
        else                      asm volatile("cp.async.wait_group 0;" ::: "memory");
        __syncthreads();

        int s = ms % STAGES;
        uint32_t abase = sbase + (uint32_t)s * STAGE_BYTES;
        uint32_t bbase = abase + 16384;

        #pragma unroll
        for (int ks = 0; ks < 4; ks++) {      // 4 x k32 = K128 per stage
            uint32_t afr[4][4];
            #pragma unroll
            for (int mt = 0; mt < 4; mt++) {
                uint32_t off = (a_row + mt * 16) * 128 + ks * 32 + a_hi;
                ldsm4(afr[mt], abase + sw128(off));
            }
            uint32_t bfr[2][4];
            #pragma unroll
            for (int p = 0; p < 2; p++) {
                uint32_t off = (b_row + p * 16) * 128 + ks * 32 + b_hi;
                ldsm4(bfr[p], bbase + sw128(off));
            }
            #pragma unroll
            for (int mt = 0; mt < 4; mt++)
                #pragma unroll
                for (int nt = 0; nt < 4; nt++)
                    mma_fp8(acc[mt * 4 + nt], afr[mt],
                            bfr[nt >> 1][(nt & 1) * 2], bfr[nt >> 1][(nt & 1) * 2 + 1]);
        }
        __syncthreads();

        if (load_step < nstep) {
            issue_loads(sbase, load_step % STAGES, load_step, gA0, gB0, ld, tid);
            asm volatile("cp.async.commit_group;" ::: "memory");
            load_step++;
        }
    }

    // ---------------- epilogue ----------------
    if (is_cov) {
        float* G = g_covp[split];
        #pragma unroll
        for (int mt = 0; mt < 4; mt++) {
            int gr0 = i0 + wm * 64 + mt * 16 + (lane >> 2);
            #pragma unroll
            for (int nt = 0; nt < 4; nt++) {
                int gc = j0 + wn * 32 + nt * 8 + (lane & 3) * 2;
                float* p0 = G + (size_t)gr0 * CF + gc;
                float* p1 = G + (size_t)(gr0 + 8) * CF + gc;
                *(float2*)p0 = make_float2(acc[mt * 4 + nt][0], acc[mt * 4 + nt][1]);
                *(float2*)p1 = make_float2(acc[mt * 4 + nt][2], acc[mt * 4 + nt][3]);
            }
        }
    } else {
        float lsum = 0.f;
        #pragma unroll
        for (int mt = 0; mt < 4; mt++) {
            int gr0 = i0 + wm * 64 + mt * 16 + (lane >> 2);
            #pragma unroll
            for (int nt = 0; nt < 4; nt++) {
                int gc = j0 + wn * 32 + nt * 8 + (lane & 3) * 2;
                #pragma unroll
                for (int e = 0; e < 4; e++) {
                    int gr = gr0 + (e >> 1) * 8;
                    int gcc = gc + (e & 1);
                    if (gr < NCLS && gcc < NCLS) {
                        float d = fmaf(acc[mt * 4 + nt][e], WSCALE2_INV, -(gr == gcc ? 1.f : 0.f));
                        lsum = fmaf(d, d, lsum);
                    }
                }
            }
        }
        lsum = warpSum(lsum);
        __shared__ float red[8];
        if (lane == 0) red[wid] = lsum;
        __syncthreads();
        if (tid == 0) {
            float a = 0.f;
            #pragma unroll
            for (int i = 0; i < 8; i++) a += red[i];
            float w = (ti == tj) ? 1.f : 2.f;
            atomicAdd(&g_acc[5], (double)(a * w));
        }
    }
}

// ---------------- cov loss reduce ----------------
__global__ void k_covred() {
    __shared__ double swk[8];
    const float invB = 1.0f / (float)B_ROWS;
    int tid = threadIdx.x;
    int gid = blockIdx.x * blockDim.x + tid;
    int stride = gridDim.x * blockDim.x;
    double local = 0.0;
    const int tot = CF * CF;
    for (int idx = gid; idx < tot; idx += stride) {
        int r = idx / CF, c = idx - r * CF;
        if (c > r) continue;
        float v = g_covp[0][idx] + g_covp[1][idx];
        float mu_r = g_musum[r] * invB;
        float mu_c = g_musum[c] * invB;
        float cov = fmaf(v, invB, -mu_r * mu_c);
        float d = cov - (r == c ? 1.f : 0.f);
        local += (c < r ? 2.0 : 1.0) * (double)d * (double)d;
    }
    #pragma unroll
    for (int o = 16; o; o >>= 1) local += __shfl_xor_sync(0xffffffffu, local, o);
    if ((tid & 31) == 0) swk[tid >> 5] = local;
    __syncthreads();
    if (tid == 0) {
        double a = 0.0;
        #pragma unroll
        for (int i = 0; i < 8; i++) a += swk[i];
        atomicAdd(&g_acc[4], a);
    }
}

// ---------------- finalize ----------------
__global__ void k_final(float* out) {
    if (threadIdx.x == 0 && blockIdx.x == 0) {
        double kl = 0.0;
        for (int i = 0; i < 64; i++) kl += g_klp[i];
        double nll = -g_acc[0] / (double)B_ROWS;
        kl = kl / (double)B_ROWS;
        double cov = g_acc[4];
        double ort = g_acc[5];
        double l1  = g_acc[2];
        double l2  = sqrt(g_acc[3]);
        out[0] = (float)(1.0 * nll + 0.2 * kl + 0.2 * cov + 0.1 * ort + 0.1 * l1 + 0.1 * l2);
    }
}

// ---------------- launch ----------------
extern "C" void kernel_launch(void* const* d_in, const int* in_sizes, int n_in,
                              void* d_out, int out_size) {
    const float* out_lp = nullptr;
    const void*  tgt = nullptr;
    const float* W = nullptr;
    const float* F = nullptr;
    for (int i = 0; i < n_in; i++) {
        long long sz = in_sizes[i];
        if (sz == (long long)B_ROWS * NCLS) out_lp = (const float*)d_in[i];
        else if (sz == B_ROWS)              tgt   = d_in[i];
        else if (sz == (long long)NCLS * CF) W    = (const float*)d_in[i];
        else if (sz == (long long)B_ROWS * CF) F  = (const float*)d_in[i];
    }
    if (!out_lp || !tgt || !W || !F) return;

    static int smem_set = 0;
    if (!smem_set) {
        cudaFuncSetAttribute(k_mma3, cudaFuncAttributeMaxDynamicSharedMemorySize, SMEM_MMA);
        smem_set = 1;
    }

    k_init<<<5, 256>>>();
    k_wconv<<<160, 256>>>(W);
    k_fpass<<<B_ROWS / 32, 256>>>(F);
    k_nll<<<64, 256>>>(out_lp, tgt);
    k_mma3<<<SPLITC * NT_COV + NT_ORT, 256, SMEM_MMA>>>();
    k_covred<<<256, 256>>>();
    k_final<<<1, 32>>>((float*)d_out);
}

// round 6
// speedup vs baseline: 5.0466x; 1.1354x over previous
#include <cuda_runtime.h>
#include <cuda_bf16.h>
#include <cuda_fp8.h>
#include <math.h>
#include <stdint.h>

#define B_ROWS 16384
#define NCLS   1000
#define CF     1280
#define NPAD   1024

#define NT_COV 55                 // 10x10 lower-tri 128-tiles
#define NT_ORT 36                 // 8x8 lower-tri 128-tiles
#define SPLITC 2
#define KSPLIT (B_ROWS / SPLITC)  // 8192
#define NSTEP_COV (KSPLIT / 128)  // 64
#define NSTEP_ORT (CF / 128)      // 10

#define STAGES      4
#define STAGE_BYTES 32768         // A(16KB fp8 128x128) + B(16KB)
#define SMEM_MMA    (STAGES * STAGE_BYTES)

#define WSCALE 64.0f
#define WSCALE2_INV (1.0f / 4096.0f)

#define NB_W   128                // wconv blocks in k_small
#define NB_N   64                 // nll blocks in k_small
#define NB_F   (B_ROWS / 32)      // 512 fpass blocks
#define NB_CR  256                // covred blocks

// ---------------- device scratch (all partial slots written unconditionally) ----
__device__ float  g_musum[CF];                       // zeroed by k_init (atomics)
__device__ float  g_p1[NB_W], g_p2[NB_W];            // L1 / L2^2 partials
__device__ float  g_pn[NB_N];                        // nll partials
__device__ float  g_klp2[NB_F];                      // kl per-block partials
__device__ double g_cvp[NB_CR];                      // cov loss partials
__device__ double g_otp[NT_ORT];                     // ortho per-tile partials
__device__ __align__(256) uint8_t g_Ft8[CF][B_ROWS]; // F^T e4m3
__device__ __align__(256) uint8_t g_Wb8[NPAD][CF];   // W*64 e4m3, zero-padded
__device__ float g_covp[SPLITC][CF * CF];            // SYRK split-K partials

// ---------------- helpers ----------------
__device__ __forceinline__ float warpSum(float v) {
    #pragma unroll
    for (int o = 16; o; o >>= 1) v += __shfl_xor_sync(0xffffffffu, v, o);
    return v;
}
__device__ __forceinline__ uint32_t smem_u32(const void* p) {
    uint32_t a;
    asm("{ .reg .u64 t; cvta.to.shared.u64 t, %1; cvt.u32.u64 %0, t; }" : "=r"(a) : "l"(p));
    return a;
}
__device__ __forceinline__ uint32_t sw128(uint32_t off) {
    return off ^ ((off >> 3) & 0x70);
}
__device__ __forceinline__ void cp16(uint32_t saddr, const void* g) {
    asm volatile("cp.async.cg.shared.global [%0], [%1], 16;" :: "r"(saddr), "l"(g) : "memory");
}
__device__ __forceinline__ void ldsm4(uint32_t* r, uint32_t addr) {
    asm volatile("ldmatrix.sync.aligned.m8n8.x4.shared.b16 {%0,%1,%2,%3}, [%4];"
                 : "=r"(r[0]), "=r"(r[1]), "=r"(r[2]), "=r"(r[3]) : "r"(addr));
}
__device__ __forceinline__ void mma_fp8(float* d, const uint32_t* a, uint32_t b0, uint32_t b1) {
    asm volatile(
        "mma.sync.aligned.m16n8k32.row.col.f32.e4m3.e4m3.f32 "
        "{%0,%1,%2,%3}, {%4,%5,%6,%7}, {%8,%9}, {%0,%1,%2,%3};"
        : "+f"(d[0]), "+f"(d[1]), "+f"(d[2]), "+f"(d[3])
        : "r"(a[0]), "r"(a[1]), "r"(a[2]), "r"(a[3]), "r"(b0), "r"(b1));
}
// pack 4 floats -> 4 e4m3 bytes (byte i = value i)
__device__ __forceinline__ uint32_t pack4_e4m3(float a0, float a1, float a2, float a3) {
    uint16_t lo, hi;
    asm("cvt.rn.satfinite.e4m3x2.f32 %0, %1, %2;" : "=h"(lo) : "f"(a1), "f"(a0));
    asm("cvt.rn.satfinite.e4m3x2.f32 %0, %1, %2;" : "=h"(hi) : "f"(a3), "f"(a2));
    return (uint32_t)lo | ((uint32_t)hi << 16);
}

// ---------------- init: zero g_musum (only buffer needing pre-zero) --------
__global__ void k_init() {
    int t = blockIdx.x * blockDim.x + threadIdx.x;
    if (t < CF) g_musum[t] = 0.f;
}

// ---------------- merged small kernel: wconv (blocks<NB_W) + nll ----------
__global__ __launch_bounds__(256) void k_small(const float* __restrict__ W,
                                               const float* __restrict__ out,
                                               const void* __restrict__ tgtraw) {
    int tid = threadIdx.x;
    if (blockIdx.x < NB_W) {
        // ---- W convert (x64 -> e4m3) + L1/L2 partials ----
        __shared__ float s1[8], s2[8];
        int gid = blockIdx.x * 256 + tid;
        int stride = NB_W * 256;
        float a = 0.f, q = 0.f;
        const int nf4 = NCLS * CF / 4;          // 320000 float4s
        for (int i = gid; i < nf4; i += stride) {
            float4 w = *((const float4*)W + i);
            a += (fabsf(w.x) + fabsf(w.y)) + (fabsf(w.z) + fabsf(w.w));
            q = fmaf(w.x, w.x, fmaf(w.y, w.y, fmaf(w.z, w.z, fmaf(w.w, w.w, q))));
            *(uint32_t*)&g_Wb8[0][i * 4] = pack4_e4m3(w.x * WSCALE, w.y * WSCALE,
                                                      w.z * WSCALE, w.w * WSCALE);
        }
        // zero pad rows [NCLS, NPAD)
        const int padw = (NPAD - NCLS) * CF / 4;  // 7680 words
        for (int i = gid; i < padw; i += stride)
            *((uint32_t*)&g_Wb8[NCLS][0] + i) = 0u;
        a = warpSum(a); q = warpSum(q);
        if ((tid & 31) == 0) { s1[tid >> 5] = a; s2[tid >> 5] = q; }
        __syncthreads();
        if (tid == 0) {
            float aa = 0.f, qq = 0.f;
            #pragma unroll
            for (int i = 0; i < 8; i++) { aa += s1[i]; qq += s2[i]; }
            g_p1[blockIdx.x] = aa;
            g_p2[blockIdx.x] = qq;
        }
    } else {
        // ---- nll gather (dtype-robust probe) ----
        __shared__ float swk[8];
        __shared__ int s_is64;
        const int* t32 = (const int*)tgtraw;
        if (tid == 0) {
            int all0 = 1;
            #pragma unroll
            for (int k = 0; k < 32; k++) all0 &= (t32[2 * k + 1] == 0);
            s_is64 = all0;
        }
        __syncthreads();
        int is64 = s_is64;
        int b0 = blockIdx.x - NB_W;
        int gid = b0 * 256 + tid;
        int stride = NB_N * 256;
        float v = 0.f;
        for (int b = gid; b < B_ROWS; b += stride) {
            int idx = is64 ? (int)((const long long*)tgtraw)[b] : t32[b];
            idx = min(max(idx, 0), NCLS - 1);
            v += out[(size_t)b * NCLS + idx];
        }
        v = warpSum(v);
        if ((tid & 31) == 0) swk[tid >> 5] = v;
        __syncthreads();
        if (tid == 0) {
            float aa = 0.f;
            #pragma unroll
            for (int i = 0; i < 8; i++) aa += swk[i];
            g_pn[b0] = aa;
        }
    }
}

// ---------------- fused F pass: KL + colsum + transpose->e4m3 -------------
// block = 32 rows; 40 chunks of 32x32; float4 loads; double-buffered smem.
__global__ __launch_bounds__(256) void k_fpass(const float* __restrict__ F) {
    __shared__ float ts[2][32][33];
    __shared__ float srow[32];
    int r0 = blockIdx.x * 32;
    int t = threadIdx.x;
    int lane = t & 31;
    int r  = t >> 3;            // row this thread loads (0..31)
    int c4 = (t & 7) * 4;       // col offset within chunk
    int cc = t >> 3;            // column this thread outputs
    int rs = (t & 7) * 4;       // row segment for output

    const float4* frow = (const float4*)(F + (size_t)(r0 + r) * CF);
    float sx = 0.f, se = 0.f, sex = 0.f;

    for (int ch = 0; ch < 40; ch++) {
        int buf = ch & 1;
        float4 v = frow[ch * 8 + (t & 7)];
        float e0 = __expf(v.x), e1 = __expf(v.y), e2 = __expf(v.z), e3 = __expf(v.w);
        sx += (v.x + v.y) + (v.z + v.w);
        se += (e0 + e1) + (e2 + e3);
        sex = fmaf(e0, v.x, fmaf(e1, v.y, fmaf(e2, v.z, fmaf(e3, v.w, sex))));
        ts[buf][r][c4 + 0] = v.x;
        ts[buf][r][c4 + 1] = v.y;
        ts[buf][r][c4 + 2] = v.z;
        ts[buf][r][c4 + 3] = v.w;
        __syncthreads();
        float a0 = ts[buf][rs + 0][cc];
        float a1 = ts[buf][rs + 1][cc];
        float a2 = ts[buf][rs + 2][cc];
        float a3 = ts[buf][rs + 3][cc];
        // column partial sum, reduce over the 8 lanes sharing cc
        float cs = (a0 + a1) + (a2 + a3);
        cs += __shfl_down_sync(0xffffffffu, cs, 4);
        cs += __shfl_down_sync(0xffffffffu, cs, 2);
        cs += __shfl_down_sync(0xffffffffu, cs, 1);
        if ((lane & 7) == 0) atomicAdd(&g_musum[ch * 32 + cc], cs);
        *(uint32_t*)&g_Ft8[ch * 32 + cc][r0 + rs] = pack4_e4m3(a0, a1, a2, a3);
    }

    // KL reduce across the 8 lanes sharing row r
    sx  += __shfl_down_sync(0xffffffffu, sx, 4);
    sx  += __shfl_down_sync(0xffffffffu, sx, 2);
    sx  += __shfl_down_sync(0xffffffffu, sx, 1);
    se  += __shfl_down_sync(0xffffffffu, se, 4);
    se  += __shfl_down_sync(0xffffffffu, se, 2);
    se  += __shfl_down_sync(0xffffffffu, se, 1);
    sex += __shfl_down_sync(0xffffffffu, sex, 4);
    sex += __shfl_down_sync(0xffffffffu, sex, 2);
    sex += __shfl_down_sync(0xffffffffu, sex, 1);
    if ((lane & 7) == 0) srow[r] = (float)CF * (sex / se) - sx;
    __syncthreads();
    if (t < 32) {
        float rv = srow[t];
        rv = warpSum(rv);
        if (t == 0) g_klp2[blockIdx.x] = rv;
    }
}

// ---------------- merged fp8 MMA: cov SYRK (split-K 2) + ortho ------------
__device__ __forceinline__ void issue_loads(uint32_t sbase, int s, int step,
                                            const uint8_t* gA0, const uint8_t* gB0,
                                            int ld, int tid) {
    uint32_t tbase = sbase + (uint32_t)s * STAGE_BYTES;
    const uint8_t* gA = gA0 + (size_t)step * 128;
    const uint8_t* gB = gB0 + (size_t)step * 128;
    #pragma unroll
    for (int i = 0; i < 4; i++) {
        int q = tid + i * 256;            // 0..1023
        int r = q >> 3, u = q & 7;        // 128 rows x 8 chunks(16B)
        uint32_t so = sw128((uint32_t)(r * 128 + u * 16));
        cp16(tbase + so, gA + (size_t)r * ld + u * 16);
        cp16(tbase + 16384 + so, gB + (size_t)r * ld + u * 16);
    }
}

__global__ __launch_bounds__(256, 1) void k_mma3() {
    extern __shared__ char dsm[];
    uint32_t sbase = smem_u32(dsm);
    int tid = threadIdx.x, wid = tid >> 5, lane = tid & 31;
    int bid = blockIdx.x;

    bool is_cov = bid < SPLITC * NT_COV;
    int split = is_cov ? (bid >= NT_COV ? 1 : 0) : 0;
    int t = is_cov ? (bid - split * NT_COV) : (bid - SPLITC * NT_COV);
    int ti = 0;
    while ((ti + 1) * (ti + 2) / 2 <= t) ++ti;
    int tj = t - ti * (ti + 1) / 2;
    int i0 = ti * 128, j0 = tj * 128;

    const uint8_t* src = is_cov ? &g_Ft8[0][0] : &g_Wb8[0][0];
    const int ld = is_cov ? B_ROWS : CF;
    const int nstep = is_cov ? NSTEP_COV : NSTEP_ORT;
    const size_t koff = is_cov ? (size_t)split * KSPLIT : 0;

    const uint8_t* gA0 = src + (size_t)i0 * ld + koff;
    const uint8_t* gB0 = src + (size_t)j0 * ld + koff;

    int wm = wid >> 2, wn = wid & 3;   // warp tile 64(m) x 32(n)

    float acc[16][4];
    #pragma unroll
    for (int i = 0; i < 16; i++)
        #pragma unroll
        for (int j = 0; j < 4; j++) acc[i][j] = 0.f;

    uint32_t a_row = (uint32_t)(wm * 64 + (lane & 15));
    uint32_t a_hi  = (uint32_t)((lane >> 4) * 16);
    uint32_t b_row = (uint32_t)(wn * 32 + (((lane >> 4) & 1) << 3) + (lane & 7));
    uint32_t b_hi  = (uint32_t)(((lane >> 3) & 1) * 16);

    // prologue: fill STAGES-1 = 3 stages
    int load_step = 0;
    #pragma unroll
    for (; load_step < STAGES - 1; load_step++) {
        issue_loads(sbase, load_step, load_step, gA0, gB0, ld, tid);
        asm volatile("cp.async.commit_group;" ::: "memory");
    }

    for (int ms = 0; ms < nstep; ms++) {
        // ensure group ms arrived (allowed outstanding = min(2, nstep-1-ms))
        if (ms + 3 <= nstep)      asm volatile("cp.async.wait_group 2;" ::: "memory");
        else if (ms + 2 == nstep) asm volatile("cp.async.wait_group 1;" ::: "memory");
        else                      asm volatile("cp.async.wait_group 0;" ::: "memory");
        __syncthreads();   // also guarantees all warps finished compute of ms-1

        // refill the stage freed last iteration ((ms-1) mod STAGES)
        if (load_step < nstep) {
            issue_loads(sbase, load_step % STAGES, load_step, gA0, gB0, ld, tid);
            asm volatile("cp.async.commit_group;" ::: "memory");
            load_step++;
        }

        int s = ms % STAGES;
        uint32_t abase = sbase + (uint32_t)s * STAGE_BYTES;
        uint32_t bbase = abase + 16384;

        #pragma unroll
        for (int ks = 0; ks < 4; ks++) {      // 4 x k32 = K128 per stage
            uint32_t afr[4][4];
            #pragma unroll
            for (int mt = 0; mt < 4; mt++) {
                uint32_t off = (a_row + mt * 16) * 128 + ks * 32 + a_hi;
                ldsm4(afr[mt], abase + sw128(off));
            }
            uint32_t bfr[2][4];
            #pragma unroll
            for (int p = 0; p < 2; p++) {
                uint32_t off = (b_row + p * 16) * 128 + ks * 32 + b_hi;
                ldsm4(bfr[p], bbase + sw128(off));
            }
            #pragma unroll
            for (int mt = 0; mt < 4; mt++)
                #pragma unroll
                for (int nt = 0; nt < 4; nt++)
                    mma_fp8(acc[mt * 4 + nt], afr[mt],
                            bfr[nt >> 1][(nt & 1) * 2], bfr[nt >> 1][(nt & 1) * 2 + 1]);
        }
    }

    // ---------------- epilogue ----------------
    if (is_cov) {
        float* G = g_covp[split];
        #pragma unroll
        for (int mt = 0; mt < 4; mt++) {
            int gr0 = i0 + wm * 64 + mt * 16 + (lane >> 2);
            #pragma unroll
            for (int nt = 0; nt < 4; nt++) {
                int gc = j0 + wn * 32 + nt * 8 + (lane & 3) * 2;
                float* p0 = G + (size_t)gr0 * CF + gc;
                float* p1 = G + (size_t)(gr0 + 8) * CF + gc;
                *(float2*)p0 = make_float2(acc[mt * 4 + nt][0], acc[mt * 4 + nt][1]);
                *(float2*)p1 = make_float2(acc[mt * 4 + nt][2], acc[mt * 4 + nt][3]);
            }
        }
    } else {
        float lsum = 0.f;
        #pragma unroll
        for (int mt = 0; mt < 4; mt++) {
            int gr0 = i0 + wm * 64 + mt * 16 + (lane >> 2);
            #pragma unroll
            for (int nt = 0; nt < 4; nt++) {
                int gc = j0 + wn * 32 + nt * 8 + (lane & 3) * 2;
                #pragma unroll
                for (int e = 0; e < 4; e++) {
                    int gr = gr0 + (e >> 1) * 8;
                    int gcc = gc + (e & 1);
                    if (gr < NCLS && gcc < NCLS) {
                        float d = fmaf(acc[mt * 4 + nt][e], WSCALE2_INV, -(gr == gcc ? 1.f : 0.f));
                        lsum = fmaf(d, d, lsum);
                    }
                }
            }
        }
        lsum = warpSum(lsum);
        __shared__ float red[8];
        if (lane == 0) red[wid] = lsum;
        __syncthreads();
        if (tid == 0) {
            float a = 0.f;
            #pragma unroll
            for (int i = 0; i < 8; i++) a += red[i];
            float w = (ti == tj) ? 1.f : 2.f;
            g_otp[bid - SPLITC * NT_COV] = (double)(a * w);
        }
    }
}

// ---------------- cov loss reduce (row-wise lower triangle) ---------------
__global__ __launch_bounds__(256) void k_covred() {
    __shared__ double swk[8];
    const float invB = 1.0f / (float)B_ROWS;
    int tid = threadIdx.x;
    double local = 0.0;
    for (int r = blockIdx.x; r < CF; r += NB_CR) {
        float mur = g_musum[r] * invB;
        const float* row0 = &g_covp[0][(size_t)r * CF];
        const float* row1 = &g_covp[1][(size_t)r * CF];
        for (int c = tid; c <= r; c += 256) {
            float v = row0[c] + row1[c];
            float muc = g_musum[c] * invB;
            float cov = fmaf(v, invB, -mur * muc);
            float d = cov - (r == c ? 1.f : 0.f);
            float wgt = (c < r) ? 2.f : 1.f;
            local += (double)(wgt * d * d);
        }
    }
    #pragma unroll
    for (int o = 16; o; o >>= 1) local += __shfl_xor_sync(0xffffffffu, local, o);
    if ((tid & 31) == 0) swk[tid >> 5] = local;
    __syncthreads();
    if (tid == 0) {
        double a = 0.0;
        #pragma unroll
        for (int i = 0; i < 8; i++) a += swk[i];
        g_cvp[blockIdx.x] = a;
    }
}

// ---------------- finalize: reduce all partial slots ----------------------
__global__ void k_final(float* out) {
    __shared__ double sred[8][6];
    int tid = threadIdx.x, lane = tid & 31, wid = tid >> 5;
    double nll = 0, l1 = 0, l2q = 0, kl = 0, cov = 0, ort = 0;
    for (int i = tid; i < NB_N;  i += 256) nll += (double)g_pn[i];
    for (int i = tid; i < NB_W;  i += 256) { l1 += (double)g_p1[i]; l2q += (double)g_p2[i]; }
    for (int i = tid; i < NB_F;  i += 256) kl  += (double)g_klp2[i];
    for (int i = tid; i < NB_CR; i += 256) cov += g_cvp[i];
    for (int i = tid; i < NT_ORT; i += 256) ort += g_otp[i];
    #pragma unroll
    for (int o = 16; o; o >>= 1) {
        nll += __shfl_xor_sync(0xffffffffu, nll, o);
        l1  += __shfl_xor_sync(0xffffffffu, l1, o);
        l2q += __shfl_xor_sync(0xffffffffu, l2q, o);
        kl  += __shfl_xor_sync(0xffffffffu, kl, o);
        cov += __shfl_xor_sync(0xffffffffu, cov, o);
        ort += __shfl_xor_sync(0xffffffffu, ort, o);
    }
    if (lane == 0) {
        sred[wid][0] = nll; sred[wid][1] = l1; sred[wid][2] = l2q;
        sred[wid][3] = kl;  sred[wid][4] = cov; sred[wid][5] = ort;
    }
    __syncthreads();
    if (tid == 0) {
        double a[6] = {0, 0, 0, 0, 0, 0};
        for (int i = 0; i < 8; i++)
            for (int j = 0; j < 6; j++) a[j] += sred[i][j];
        double loss = -a[0] / (double)B_ROWS            // nll
                    + 0.2 * (a[3] / (double)B_ROWS)     // kl
                    + 0.2 * a[4]                        // cov
                    + 0.1 * a[5]                        // ortho
                    + 0.1 * a[1]                        // l1
                    + 0.1 * sqrt(a[2]);                 // l2
        out[0] = (float)loss;
    }
}

// ---------------- launch ----------------
extern "C" void kernel_launch(void* const* d_in, const int* in_sizes, int n_in,
                              void* d_out, int out_size) {
    const float* out_lp = nullptr;
    const void*  tgt = nullptr;
    const float* W = nullptr;
    const float* F = nullptr;
    for (int i = 0; i < n_in; i++) {
        long long sz = in_sizes[i];
        if (sz == (long long)B_ROWS * NCLS) out_lp = (const float*)d_in[i];
        else if (sz == B_ROWS)              tgt   = d_in[i];
        else if (sz == (long long)NCLS * CF) W    = (const float*)d_in[i];
        else if (sz == (long long)B_ROWS * CF) F  = (const float*)d_in[i];
    }
    if (!out_lp || !tgt || !W || !F) return;

    static int smem_set = 0;
    if (!smem_set) {
        cudaFuncSetAttribute(k_mma3, cudaFuncAttributeMaxDynamicSharedMemorySize, SMEM_MMA);
        smem_set = 1;
    }

    k_init<<<5, 256>>>();                                   // 1
    k_small<<<NB_W + NB_N, 256>>>(W, out_lp, tgt);          // 2
    k_fpass<<<NB_F, 256>>>(F);                              // 3
    k_mma3<<<SPLITC * NT_COV + NT_ORT, 256, SMEM_MMA>>>();  // 4  <- ncu slot
    k_covred<<<NB_CR, 256>>>();                             // 5
    k_final<<<1, 256>>>((float*)d_out);                     // 6
}